// round 1
// baseline (speedup 1.0000x reference)
#include <cuda_runtime.h>
#include <cstdint>

#define FULLMASK 0xffffffffu
#define NW 32
#define INFV 1000000000.0f

// order-preserving float -> uint map (monotonic): enables integer min-reduce
__device__ __forceinline__ unsigned ford(float f) {
    unsigned u = __float_as_uint(f);
    return (u & 0x80000000u) ? ~u : (u | 0x80000000u);
}

struct Feat {
    float cx, cy, area, sr, ar, bx, by, prob;
};

__device__ __forceinline__ Feat wall_features(const float* __restrict__ q) {
    float sx = q[0], sy = q[1], ex = q[2], ey = q[3], w = q[4], prob = q[5];
    float dx = ex - sx, dy = ey - sy;
    float len = sqrtf(dx * dx + dy * dy);
    float cx = (sx + ex) * 0.5f, cy = (sy + ey) * 0.5f;
    float area = len * w;
    // side_ratio(width, len)
    float smaller = fminf(w, len), bigger = fmaxf(w, len);
    float sr = (bigger > 0.0f) ? (smaller / bigger) : 0.0f;
    // bounding box: per = (dy, -dx), normalized by |per|=len if len>0, scaled by w/2
    float px, py;
    if (len > 0.0f) {
        float s = w * 0.5f / len;
        px = dy * s;
        py = -dx * s;
    } else {
        px = 0.0f;  // dif == 0 -> per == (0,0)
        py = 0.0f;
    }
    float right = fmaxf(fmaxf(sx + px, sx - px), fmaxf(ex + px, ex - px));
    float top   = fmaxf(fmaxf(sy + py, sy - py), fmaxf(ey + py, ey - py));
    float bbw = fabsf((right - cx) * 2.0f);
    float bbh = fabsf((top  - cy) * 2.0f);
    float bba = bbw * bbh;
    float ar = (bba > 0.001f) ? (area / bba) : 1.0f;
    Feat f;
    f.cx = cx; f.cy = cy; f.area = area; f.sr = sr; f.ar = ar;
    f.bx = bbw; f.by = bbh; f.prob = prob;
    return f;
}

// One warp per batch. Cost matrix in shared (row-major, 32x32).
// Hungarian (Jonker-Volgenant shortest augmenting path), columns mapped to lanes.
__global__ void __launch_bounds__(32)
floorplanet_kernel(const float* __restrict__ params_true,
                   const float* __restrict__ params_pred,
                   float* __restrict__ out) {
    __shared__ float C[NW * NW];

    const int b = blockIdx.x;
    const int lane = threadIdx.x;

    const float* tq = params_true + (size_t)b * NW * 6 + lane * 6;
    const float* pq = params_pred + (size_t)b * NW * 6 + lane * 6;

    Feat ft = wall_features(tq);  // true wall = lane (row features)
    Feat fp = wall_features(pq);  // pred wall = lane (col features)

    // Fill C[i][lane]: broadcast row-i true-features via shfl, lane holds pred col.
#pragma unroll 4
    for (int i = 0; i < NW; i++) {
        float icx   = __shfl_sync(FULLMASK, ft.cx,   i);
        float icy   = __shfl_sync(FULLMASK, ft.cy,   i);
        float iarea = __shfl_sync(FULLMASK, ft.area, i);
        float isr   = __shfl_sync(FULLMASK, ft.sr,   i);
        float iar   = __shfl_sync(FULLMASK, ft.ar,   i);
        float ibx   = __shfl_sync(FULLMASK, ft.bx,   i);
        float iby   = __shfl_sync(FULLMASK, ft.by,   i);
        float iprob = __shfl_sync(FULLMASK, ft.prob, i);

        float dcx = icx - fp.cx, dcy = icy - fp.cy;
        float center_d = dcx * dcx + dcy * dcy;
        float da = iarea - fp.area;  float area_d  = da * da;
        float ds = isr   - fp.sr;    float lwr_d   = ds * ds;
        float dr = iar   - fp.ar;    float rot_d   = dr * dr;
        float dh = ibx   - fp.bx;    float horiz_d = dh * dh;
        float dv = iby   - fp.by;    float vert_d  = dv * dv;
        float dp = iprob - fp.prob;  float prob_d  = dp * dp;

        float param_d = area_d + center_d + rot_d + horiz_d + vert_d + lwr_d;
        C[i * NW + lane] = 10.0f * prob_d + param_d * iprob;
    }
    __syncwarp();

    // ---- Hungarian (JV). Lane-resident state:
    //   u[lane]        row dual        v[lane]       col dual
    //   col4row[lane]  row->col match  row4col[lane] col->row match
    float u = 0.0f, v = 0.0f;
    int col4row = -1, row4col = -1;

    for (int i0 = 0; i0 < NW; i0++) {
        unsigned SR = 0u, SC = 0u;      // row/col visited masks (warp-uniform)
        float spc = INFV;               // shortestPathCosts[lane]
        int   path = -1;                // path[lane]
        float minVal = 0.0f;
        int i = i0, sink = -1;

        while (sink < 0) {
            SR |= 1u << i;
            float ui = __shfl_sync(FULLMASK, u, i);
            float slack = minVal + C[i * NW + lane] - ui - v;
            bool notSC = ((SC >> lane) & 1u) == 0u;
            if (notSC && slack < spc) { spc = slack; path = i; }
            float masked = notSC ? spc : INFV;

            // argmin over lanes, first-index tie-break (matches jnp.argmin)
            unsigned ok = ford(masked);
            unsigned om = __reduce_min_sync(FULLMASK, ok);
            unsigned bal = __ballot_sync(FULLMASK, ok == om);
            int j = __ffs(bal) - 1;
            minVal = __shfl_sync(FULLMASK, masked, j);

            SC |= 1u << j;
            int r = __shfl_sync(FULLMASK, row4col, j);
            if (r < 0) sink = j;
            i = r;
        }

        // dual updates (before augmentation, as in reference)
        float spc_c4r = __shfl_sync(FULLMASK, spc, col4row & 31);
        bool inSR = ((SR >> lane) & 1u) != 0u;
        if (inSR && lane != i0) u += minVal - spc_c4r;
        if (lane == i0) u += minVal;
        if ((SC >> lane) & 1u) v -= minVal - spc;

        // augment along path (warp-uniform scalar walk)
        int j = sink;
        bool done = false;
        while (!done) {
            int pi = __shfl_sync(FULLMASK, path, j);     // path[j]
            if (lane == j) row4col = pi;
            int jn = __shfl_sync(FULLMASK, col4row, pi); // col4row[pi] (pre-update)
            if (lane == pi) col4row = j;
            done = (pi == i0);
            j = jn;
        }
    }

    // loss = sum_i C[i][col4row[i]]
    float c = C[lane * NW + (col4row & 31)];
#pragma unroll
    for (int off = 16; off > 0; off >>= 1)
        c += __shfl_xor_sync(FULLMASK, c, off);
    if (lane == 0) out[b] = c;
}

extern "C" void kernel_launch(void* const* d_in, const int* in_sizes, int n_in,
                              void* d_out, int out_size) {
    const float* params_true = (const float*)d_in[0];
    const float* params_pred = (const float*)d_in[1];
    float* out = (float*)d_out;
    (void)in_sizes; (void)n_in; (void)out_size;
    floorplanet_kernel<<<2048, 32>>>(params_true, params_pred, out);
}

// round 2
// speedup vs baseline: 1.2884x; 1.2884x over previous
#include <cuda_runtime.h>
#include <cstdint>

#define FM 0xffffffffu
#define NW 32
#define INFV 1000000000.0f

// order-preserving float <-> uint maps (monotonic), enabling integer min-reduce
__device__ __forceinline__ unsigned ford(float f) {
    unsigned u = __float_as_uint(f);
    return u ^ (unsigned)(((int)u >> 31) | 0x80000000);
}
__device__ __forceinline__ float iford(unsigned k) {
    unsigned u = k ^ (unsigned)(((int)(~k) >> 31) | 0x80000000);
    return __uint_as_float(u);
}

struct Feat {
    float cx, cy, area, sr, ar, bx, by, prob;
};

__device__ __forceinline__ Feat wall_features(const float* __restrict__ q) {
    float sx = q[0], sy = q[1], ex = q[2], ey = q[3], w = q[4], prob = q[5];
    float dx = ex - sx, dy = ey - sy;
    float len = sqrtf(dx * dx + dy * dy);
    float cx = (sx + ex) * 0.5f, cy = (sy + ey) * 0.5f;
    float area = len * w;
    float smaller = fminf(w, len), bigger = fmaxf(w, len);
    float sr = (bigger > 0.0f) ? (smaller / bigger) : 0.0f;
    float px, py;
    if (len > 0.0f) {
        float s = w * 0.5f / len;
        px = dy * s;
        py = -dx * s;
    } else {
        px = 0.0f;
        py = 0.0f;
    }
    float right = fmaxf(fmaxf(sx + px, sx - px), fmaxf(ex + px, ex - px));
    float top   = fmaxf(fmaxf(sy + py, sy - py), fmaxf(ey + py, ey - py));
    float bbw = fabsf((right - cx) * 2.0f);
    float bbh = fabsf((top  - cy) * 2.0f);
    float bba = bbw * bbh;
    float ar = (bba > 0.001f) ? (area / bba) : 1.0f;
    Feat f;
    f.cx = cx; f.cy = cy; f.area = area; f.sr = sr; f.ar = ar;
    f.bx = bbw; f.by = bbh; f.prob = prob;
    return f;
}

// One warp per batch. Columns (pred walls) <-> lanes.
// JV: column-reduction init + shortest augmenting paths for remaining free rows.
__global__ void __launch_bounds__(32)
floorplanet_kernel(const float* __restrict__ params_true,
                   const float* __restrict__ params_pred,
                   float* __restrict__ out) {
    __shared__ float C[NW * NW];
    __shared__ int c4r_sh[NW];

    const int b = blockIdx.x;
    const int lane = threadIdx.x;

    Feat ft = wall_features(params_true + (size_t)b * NW * 6 + lane * 6);
    Feat fp = wall_features(params_pred + (size_t)b * NW * 6 + lane * 6);

    // Fill C[i][lane] and track column min/argmin on the fly.
    float cm = INFV;
    int am = 0;
#pragma unroll 4
    for (int i = 0; i < NW; i++) {
        float icx   = __shfl_sync(FM, ft.cx,   i);
        float icy   = __shfl_sync(FM, ft.cy,   i);
        float iarea = __shfl_sync(FM, ft.area, i);
        float isr   = __shfl_sync(FM, ft.sr,   i);
        float iar   = __shfl_sync(FM, ft.ar,   i);
        float ibx   = __shfl_sync(FM, ft.bx,   i);
        float iby   = __shfl_sync(FM, ft.by,   i);
        float iprob = __shfl_sync(FM, ft.prob, i);

        float dcx = icx - fp.cx, dcy = icy - fp.cy;
        float center_d = dcx * dcx + dcy * dcy;
        float da = iarea - fp.area;
        float ds = isr   - fp.sr;
        float dr = iar   - fp.ar;
        float dh = ibx   - fp.bx;
        float dv = iby   - fp.by;
        float dp = iprob - fp.prob;

        float param_d = da * da + center_d + dr * dr + dh * dh + dv * dv + ds * ds;
        float cost = 10.0f * (dp * dp) + param_d * iprob;
        C[i * NW + lane] = cost;
        if (cost < cm) { cm = cost; am = i; }
    }
    __syncwarp();

    // ---- Column reduction: v[j] = colmin; greedily match each column's argmin
    // row; among columns claiming the same row the lowest lane wins.
    float v = cm, u = 0.0f;
    unsigned grp = __match_any_sync(FM, am);
    bool winner = ((__ffs(grp) - 1) == lane);
    int row4col = winner ? am : -1;   // column lane -> matched row
    c4r_sh[lane] = -1;
    __syncwarp();
    if (winner) c4r_sh[am] = lane;
    __syncwarp();
    int col4row = c4r_sh[lane];       // row lane -> matched column
    unsigned freerows = __ballot_sync(FM, col4row < 0);

    // ---- Shortest augmenting path for each free row.
    while (freerows) {
        const int i0 = __ffs(freerows) - 1;
        freerows &= freerows - 1;

        unsigned SR = 0u, SC = 0u;
        float spc = INFV;                 // frozen at selection for SC lanes
        unsigned mkey = 0xFFFFFFFFu;      // redux operand (UINT_MAX == masked)
        int path = -1;
        float minVal = 0.0f;
        float mvv = -v;                   // minVal - v (lane-local)
        int i = i0, sink = -1;

        do {
            SR |= 1u << i;
            float ui = __shfl_sync(FM, u, i);
            float cv = C[i * NW + lane];
            float slack = (cv - ui) + mvv;
            bool notSC = ((SC >> lane) & 1u) == 0u;
            unsigned skey = notSC ? ford(slack) : 0xFFFFFFFFu;
            if (skey < mkey) { mkey = skey; spc = slack; path = i; }

            unsigned om = __reduce_min_sync(FM, mkey);
            minVal = iford(om);
            mvv = minVal - v;
            unsigned bal = __ballot_sync(FM, mkey == om);
            int j = __ffs(bal) - 1;

            SC |= 1u << j;
            if (lane == j) mkey = 0xFFFFFFFFu;  // spc stays frozen for duals
            int r = __shfl_sync(FM, row4col, j);
            sink = (r < 0) ? j : -1;
            i = r;
        } while (sink < 0);

        // Dual updates.
        float spc_c4r = __shfl_sync(FM, spc, col4row & 31);
        if ((SR >> lane) & 1u) u += (lane == i0) ? minVal : (minVal - spc_c4r);
        if ((SC >> lane) & 1u) v -= minVal - spc;

        // Augment along the alternating path.
        int j = sink;
        bool done = false;
        while (!done) {
            int pi = __shfl_sync(FM, path, j);       // path[j]
            if (lane == j) row4col = pi;
            int jn = __shfl_sync(FM, col4row, pi);   // old col4row[pi]
            if (lane == pi) col4row = j;
            done = (pi == i0);
            j = jn;
        }
    }

    // loss = sum_i C[i][col4row[i]]  (col4row is a permutation -> conflict-free)
    float c = C[lane * NW + (col4row & 31)];
#pragma unroll
    for (int off = 16; off > 0; off >>= 1)
        c += __shfl_xor_sync(FM, c, off);
    if (lane == 0) out[b] = c;
}

extern "C" void kernel_launch(void* const* d_in, const int* in_sizes, int n_in,
                              void* d_out, int out_size) {
    const float* params_true = (const float*)d_in[0];
    const float* params_pred = (const float*)d_in[1];
    float* out = (float*)d_out;
    (void)in_sizes; (void)n_in; (void)out_size;
    floorplanet_kernel<<<2048, 32>>>(params_true, params_pred, out);
}